// round 4
// baseline (speedup 1.0000x reference)
#include <cuda_runtime.h>
#include <cuda_bf16.h>

// GCN: N=50000 nodes, E=800000 edges, 128 -> 128 -> 128 -> 64
#define NN 50000
#define EE 800000
#define CH 128
#define CO 64
#define BN_EPS 1e-5f

// ---------------- scratch (static device allocations only) ----------------
__device__ float g_deg[NN];
__device__ float g_dinv[NN];
__device__ float g_norm[EE];
__device__ float g_bufA[NN * CH];   // GEMM output h
__device__ float g_bufB[NN * CH];   // aggregation output
__device__ float g_Wt1[CH * CH];    // W transposed: [c][o]
__device__ float g_Wt2[CH * CH];
__device__ float g_Wt3[CH * CO];
__device__ float g_stats[512];      // layer1: sum[0:128), sumsq[128:256); layer2: +256
__device__ float g_aff[512];        // layer1: scale[0:128), shift[128:256); layer2: +256
__device__ int   g_idx64;           // 1 if edge_index is int64, 0 if int32

// ---------------- index load helper (int32 / int64 agnostic) ----------------
__device__ __forceinline__ int ldidx(const void* p, int i, int is64) {
    if (is64) return (int)((const long long*)p)[i];
    return ((const int*)p)[i];
}

// ---------------- init: deg=1 (self loops), zero stats, detect idx dtype ----
__global__ void k_init(const int* ei32) {
    int i = blockIdx.x * blockDim.x + threadIdx.x;
    if (i < NN) g_deg[i] = 1.0f;
    if (i < 512) g_stats[i] = 0.0f;
    if (i == 0) {
        // If data is int64 (values in [0,50000)), every odd 32-bit word of the
        // first 32 entries is 0. For random int32 indices this is ~impossible.
        int z = 1;
#pragma unroll
        for (int j = 0; j < 32; j++)
            if (ei32[2 * j + 1] != 0) z = 0;
        g_idx64 = z;
    }
}

// ---------------- transpose weights into [c][o] layout ----------------
__global__ void k_prepw(const float* __restrict__ W1, const float* __restrict__ W2,
                        const float* __restrict__ W3) {
    int i = blockIdx.x * blockDim.x + threadIdx.x;
    if (i < CH * CH) {
        int o = i / CH, c = i % CH;
        g_Wt1[c * CH + o] = W1[i];
        g_Wt2[c * CH + o] = W2[i];
    }
    if (i < CO * CH) {
        int o = i / CH, c = i % CH;
        g_Wt3[c * CO + o] = W3[i];
    }
}

// ---------------- degree accumulation (in-degree at dst, +1 self loop in init)
__global__ void k_degree(const void* __restrict__ ei) {
    int e = blockIdx.x * blockDim.x + threadIdx.x;
    if (e >= EE) return;
    int is64 = g_idx64;
    int d = ldidx(ei, EE + e, is64);
    atomicAdd(&g_deg[d], 1.0f);
}

__global__ void k_dinv() {
    int i = blockIdx.x * blockDim.x + threadIdx.x;
    if (i < NN) g_dinv[i] = rsqrtf(g_deg[i]);
}

__global__ void k_norm(const void* __restrict__ ei) {
    int e = blockIdx.x * blockDim.x + threadIdx.x;
    if (e >= EE) return;
    int is64 = g_idx64;
    int s = ldidx(ei, e, is64);
    int d = ldidx(ei, EE + e, is64);
    g_norm[e] = g_dinv[s] * g_dinv[d];
}

// ---------------- GEMM: H[n][o] = sum_c X[n][c] * Wt[c][o] ----------------
// Wt in global ([c][o], 64KB -> L1 resident). X tile transposed in shared.
// Block: 256 threads, 64 rows. Per thread: RPT rows x 4 cols register tile.
template <int OC>
__global__ void __launch_bounds__(256) k_gemm(const float* __restrict__ X,
                                              const float* __restrict__ Wt,
                                              float* __restrict__ H, int nrows) {
    constexpr int K = 128, BM = 64, XS = BM + 4;
    constexpr int TPG = OC / 4;           // threads per row-group (32 or 16)
    constexpr int RPT = BM / (256 / TPG); // rows per thread (8 or 4)
    __shared__ __align__(16) float Xs[K * XS];

    int t = threadIdx.x;
    int row0 = blockIdx.x * BM;

    // Load X tile, transposed: Xs[c][r]
#pragma unroll
    for (int j = 0; j < (BM * K) / 256; j++) {
        int idx = t + j * 256;
        int r = idx >> 7, c = idx & 127;
        int row = row0 + r;
        float v = (row < nrows) ? X[row * K + c] : 0.0f;
        Xs[c * XS + r] = v;
    }
    __syncthreads();

    int o0 = (t % TPG) * 4;
    int r0 = (t / TPG) * RPT;

    float acc[RPT][4];
#pragma unroll
    for (int j = 0; j < RPT; j++)
#pragma unroll
        for (int l = 0; l < 4; l++) acc[j][l] = 0.0f;

#pragma unroll 4
    for (int c = 0; c < K; c++) {
        const float4 wv = *reinterpret_cast<const float4*>(Wt + c * OC + o0);
#pragma unroll
        for (int jj = 0; jj < RPT / 4; jj++) {
            const float4 xv = *reinterpret_cast<const float4*>(Xs + c * XS + r0 + 4 * jj);
            float xa0 = xv.x, xa1 = xv.y, xa2 = xv.z, xa3 = xv.w;
            acc[4 * jj + 0][0] = fmaf(xa0, wv.x, acc[4 * jj + 0][0]);
            acc[4 * jj + 0][1] = fmaf(xa0, wv.y, acc[4 * jj + 0][1]);
            acc[4 * jj + 0][2] = fmaf(xa0, wv.z, acc[4 * jj + 0][2]);
            acc[4 * jj + 0][3] = fmaf(xa0, wv.w, acc[4 * jj + 0][3]);
            acc[4 * jj + 1][0] = fmaf(xa1, wv.x, acc[4 * jj + 1][0]);
            acc[4 * jj + 1][1] = fmaf(xa1, wv.y, acc[4 * jj + 1][1]);
            acc[4 * jj + 1][2] = fmaf(xa1, wv.z, acc[4 * jj + 1][2]);
            acc[4 * jj + 1][3] = fmaf(xa1, wv.w, acc[4 * jj + 1][3]);
            acc[4 * jj + 2][0] = fmaf(xa2, wv.x, acc[4 * jj + 2][0]);
            acc[4 * jj + 2][1] = fmaf(xa2, wv.y, acc[4 * jj + 2][1]);
            acc[4 * jj + 2][2] = fmaf(xa2, wv.z, acc[4 * jj + 2][2]);
            acc[4 * jj + 2][3] = fmaf(xa2, wv.w, acc[4 * jj + 2][3]);
            acc[4 * jj + 3][0] = fmaf(xa3, wv.x, acc[4 * jj + 3][0]);
            acc[4 * jj + 3][1] = fmaf(xa3, wv.y, acc[4 * jj + 3][1]);
            acc[4 * jj + 3][2] = fmaf(xa3, wv.z, acc[4 * jj + 3][2]);
            acc[4 * jj + 3][3] = fmaf(xa3, wv.w, acc[4 * jj + 3][3]);
        }
    }

#pragma unroll
    for (int j = 0; j < RPT; j++) {
        int row = row0 + r0 + j;
        if (row < nrows) {
            float4 ov = make_float4(acc[j][0], acc[j][1], acc[j][2], acc[j][3]);
            *reinterpret_cast<float4*>(H + row * OC + o0) = ov;
        }
    }
}

// ---------------- self-loop init: agg[n][c] = h[n][c]/deg[n] + bias[c] ------
template <int C>
__global__ void k_selfinit(const float4* __restrict__ h, const float* __restrict__ bias,
                           float4* __restrict__ agg) {
    constexpr int L = C / 4;
    int i = blockIdx.x * blockDim.x + threadIdx.x;
    if (i >= NN * L) return;
    int n = i / L;
    int c4 = (i % L) * 4;
    float di = g_dinv[n];
    float w = di * di;
    float4 v = h[i];
    float4 b = *reinterpret_cast<const float4*>(bias + c4);
    v.x = fmaf(v.x, w, b.x);
    v.y = fmaf(v.y, w, b.y);
    v.z = fmaf(v.z, w, b.z);
    v.w = fmaf(v.w, w, b.w);
    agg[i] = v;
}

// ---------------- edge scatter: agg[dst] += norm * h[src] ------------------
template <int C>
__global__ void k_edge(const void* __restrict__ ei, const float4* __restrict__ h,
                       float4* agg) {
    constexpr int L = C / 4;
    int g = blockIdx.x * blockDim.x + threadIdx.x;
    int e = g / L;
    int lane = g % L;
    if (e >= EE) return;
    int is64 = g_idx64;
    int s = ldidx(ei, e, is64);
    int d = ldidx(ei, EE + e, is64);
    float w = g_norm[e];
    float4 v = h[s * L + lane];
    v.x *= w; v.y *= w; v.z *= w; v.w *= w;
    atomicAdd(&agg[d * L + lane], v);   // sm_90+ vector atomic (red.global.v4.f32)
}

// ---------------- BN stats: per-channel sum & sumsq over nodes --------------
__global__ void k_stats(const float* __restrict__ buf, float* sums) {
    int t = threadIdx.x; // 128
    float s = 0.0f, ss = 0.0f;
    for (int r = blockIdx.x; r < NN; r += gridDim.x) {
        float v = buf[r * CH + t];
        s += v;
        ss += v * v;
    }
    atomicAdd(&sums[t], s);
    atomicAdd(&sums[CH + t], ss);
}

__global__ void k_finalize(const float* __restrict__ sums, const float* __restrict__ gamma,
                           const float* __restrict__ beta, float* aff) {
    int t = threadIdx.x; // 128
    const float inv = 1.0f / (float)NN;
    float mean = sums[t] * inv;
    float var = sums[CH + t] * inv - mean * mean;
    float sc = gamma[t] * rsqrtf(var + BN_EPS);
    aff[t] = sc;
    aff[CH + t] = beta[t] - mean * sc;
}

// ---------------- BN apply + ReLU, in place --------------------------------
__global__ void k_bnapply(float4* buf, const float* __restrict__ aff) {
    int i = blockIdx.x * blockDim.x + threadIdx.x;
    if (i >= NN * (CH / 4)) return;
    int c4 = (i & ((CH / 4) - 1)) * 4;
    float4 v = buf[i];
    v.x = fmaxf(fmaf(v.x, aff[c4 + 0], aff[CH + c4 + 0]), 0.0f);
    v.y = fmaxf(fmaf(v.y, aff[c4 + 1], aff[CH + c4 + 1]), 0.0f);
    v.z = fmaxf(fmaf(v.z, aff[c4 + 2], aff[CH + c4 + 2]), 0.0f);
    v.w = fmaxf(fmaf(v.w, aff[c4 + 3], aff[CH + c4 + 3]), 0.0f);
    buf[i] = v;
}

// ---------------- launch ----------------------------------------------------
extern "C" void kernel_launch(void* const* d_in, const int* in_sizes, int n_in,
                              void* d_out, int out_size) {
    const float* x  = (const float*)d_in[0];
    const void*  ei = d_in[1];
    const float* W1 = (const float*)d_in[2];
    const float* b1 = (const float*)d_in[3];
    const float* W2 = (const float*)d_in[4];
    const float* b2 = (const float*)d_in[5];
    const float* W3 = (const float*)d_in[6];
    const float* b3 = (const float*)d_in[7];
    const float* g1 = (const float*)d_in[8];
    const float* t1 = (const float*)d_in[9];
    const float* g2 = (const float*)d_in[10];
    const float* t2 = (const float*)d_in[11];
    float* out = (float*)d_out;

    void *pA_, *pB_, *pW1_, *pW2_, *pW3_, *pSt_, *pAf_;
    cudaGetSymbolAddress(&pA_, g_bufA);
    cudaGetSymbolAddress(&pB_, g_bufB);
    cudaGetSymbolAddress(&pW1_, g_Wt1);
    cudaGetSymbolAddress(&pW2_, g_Wt2);
    cudaGetSymbolAddress(&pW3_, g_Wt3);
    cudaGetSymbolAddress(&pSt_, g_stats);
    cudaGetSymbolAddress(&pAf_, g_aff);
    float* pA = (float*)pA_;
    float* pB = (float*)pB_;
    float* pW1 = (float*)pW1_;
    float* pW2 = (float*)pW2_;
    float* pW3 = (float*)pW3_;
    float* pSt = (float*)pSt_;
    float* pAf = (float*)pAf_;

    const int TPB = 256;
    const int gN  = (NN + TPB - 1) / TPB;
    const int gE  = (EE + TPB - 1) / TPB;
    const int gNC128 = (NN * (CH / 4) + TPB - 1) / TPB;   // float4 elementwise, 128ch
    const int gNC64  = (NN * (CO / 4) + TPB - 1) / TPB;   // float4 elementwise, 64ch
    const int gE128  = (EE * (CH / 4) + TPB - 1) / TPB;   // edge scatter, 128ch
    const int gE64   = (EE * (CO / 4) + TPB - 1) / TPB;   // edge scatter, 64ch
    const int gGemm  = (NN + 63) / 64;

    // preprocessing
    k_init<<<gN, TPB>>>((const int*)ei);
    k_prepw<<<(CH * CH + TPB - 1) / TPB, TPB>>>(W1, W2, W3);
    k_degree<<<gE, TPB>>>(ei);
    k_dinv<<<gN, TPB>>>();
    k_norm<<<gE, TPB>>>(ei);

    // layer 1: h = x @ W1^T ; agg = A_hat h + b1 ; BN+ReLU
    k_gemm<CH><<<gGemm, TPB>>>(x, pW1, pA, NN);
    k_selfinit<CH><<<gNC128, TPB>>>((const float4*)pA, b1, (float4*)pB);
    k_edge<CH><<<gE128, TPB>>>(ei, (const float4*)pA, (float4*)pB);
    k_stats<<<1024, 128>>>(pB, pSt);
    k_finalize<<<1, 128>>>(pSt, g1, t1, pAf);
    k_bnapply<<<gNC128, TPB>>>((float4*)pB, pAf);

    // layer 2
    k_gemm<CH><<<gGemm, TPB>>>(pB, pW2, pA, NN);
    k_selfinit<CH><<<gNC128, TPB>>>((const float4*)pA, b2, (float4*)pB);
    k_edge<CH><<<gE128, TPB>>>(ei, (const float4*)pA, (float4*)pB);
    k_stats<<<1024, 128>>>(pB, pSt + 256);
    k_finalize<<<1, 128>>>(pSt + 256, g2, t2, pAf + 256);
    k_bnapply<<<gNC128, TPB>>>((float4*)pB, pAf + 256);

    // layer 3 (64 out channels, no BN) -> d_out
    k_gemm<CO><<<gGemm, TPB>>>(pB, pW3, pA, NN);
    k_selfinit<CO><<<gNC64, TPB>>>((const float4*)pA, b3, (float4*)out);
    k_edge<CO><<<gE64, TPB>>>(ei, (const float4*)pA, (float4*)out);

    (void)in_sizes; (void)n_in; (void)out_size;
}

// round 5
// speedup vs baseline: 1.0120x; 1.0120x over previous
#include <cuda_runtime.h>
#include <cuda_bf16.h>

// GCN: N=50000 nodes, E=800000 edges, 128 -> 128 -> 128 -> 64
#define NN 50000
#define EE 800000
#define CH 128
#define CO 64
#define BN_EPS 1e-5f

// ---------------- scratch (static device allocations only) ----------------
__device__ float g_dinv[NN];
__device__ int   g_cnt[NN];          // in-degree (no self loop)
__device__ int   g_cur[NN];          // CSR fill cursors
__device__ int   g_off[NN + 1];      // CSR row offsets (by dst)
__device__ int2  g_epack[EE];        // {src, w(bits)} sorted by dst
__device__ float g_bufA[NN * CH];    // GEMM output h
__device__ float g_bufB[NN * CH];    // aggregation output
__device__ float g_Wd1[CH * CH * 2]; // W transposed + duplicated: [c][2o] (pairs)
__device__ float g_Wd2[CH * CH * 2];
__device__ float g_Wd3[CH * CO * 2];
__device__ float g_stats[512];       // L1: sum[0:128) sumsq[128:256); L2: +256
__device__ float g_aff[512];         // L1: scale[0:128) shift[128:256); L2: +256
__device__ int   g_idx64;

// ---------------- helpers ----------------
__device__ __forceinline__ int ldidx(const void* p, long long i, int is64) {
    if (is64) return (int)((const long long*)p)[i];
    return ((const int*)p)[i];
}

__device__ __forceinline__ void ffma2(unsigned long long& d, unsigned long long a,
                                      unsigned long long b) {
    // packed fp32x2 FMA: d = a*b + d (lane-wise)
    asm("fma.rn.f32x2 %0, %1, %2, %0;" : "+l"(d) : "l"(a), "l"(b));
}
__device__ __forceinline__ float f2lo(unsigned long long v) {
    return __uint_as_float((unsigned)(v & 0xffffffffull));
}
__device__ __forceinline__ float f2hi(unsigned long long v) {
    return __uint_as_float((unsigned)(v >> 32));
}

// ---------------- init: zero counters/stats, detect idx dtype ----------------
__global__ void k_init(const int* ei32) {
    int i = blockIdx.x * blockDim.x + threadIdx.x;
    if (i < NN) { g_cnt[i] = 0; g_cur[i] = 0; }
    if (i < 512) g_stats[i] = 0.0f;
    if (i == 0) {
        int z = 1;
#pragma unroll
        for (int j = 0; j < 32; j++)
            if (ei32[2 * j + 1] != 0) z = 0;
        g_idx64 = z;
    }
}

// ---------------- weights: transpose to [c][o] and duplicate each value -----
__global__ void k_prepw(const float* __restrict__ W1, const float* __restrict__ W2,
                        const float* __restrict__ W3) {
    int i = blockIdx.x * blockDim.x + threadIdx.x;
    if (i < CH * CH) {
        int o = i / CH, c = i % CH;
        float v1 = W1[i], v2 = W2[i];
        g_Wd1[c * 2 * CH + 2 * o] = v1; g_Wd1[c * 2 * CH + 2 * o + 1] = v1;
        g_Wd2[c * 2 * CH + 2 * o] = v2; g_Wd2[c * 2 * CH + 2 * o + 1] = v2;
    }
    if (i < CO * CH) {
        int o = i / CH, c = i % CH;
        float v3 = W3[i];
        g_Wd3[c * 2 * CO + 2 * o] = v3; g_Wd3[c * 2 * CO + 2 * o + 1] = v3;
    }
}

// ---------------- in-degree counting at dst ----------------
__global__ void k_degree(const void* __restrict__ ei) {
    int e = blockIdx.x * blockDim.x + threadIdx.x;
    if (e >= EE) return;
    int is64 = g_idx64;
    int d = ldidx(ei, (long long)EE + e, is64);
    atomicAdd(&g_cnt[d], 1);
}

__global__ void k_dinv() {
    int i = blockIdx.x * blockDim.x + threadIdx.x;
    if (i < NN) g_dinv[i] = rsqrtf((float)g_cnt[i] + 1.0f);
}

// ---------------- exclusive prefix sum of g_cnt -> g_off (1 block) ----------
__global__ void __launch_bounds__(1024) k_scan() {
    __shared__ int wsum[32];
    __shared__ int carry_s;
    int t = threadIdx.x, lane = t & 31, wid = t >> 5;
    if (t == 0) { carry_s = 0; g_off[0] = 0; }
    __syncthreads();
    for (int base = 0; base < NN; base += 1024) {
        int i = base + t;
        int v = (i < NN) ? g_cnt[i] : 0;
        int s = v;
#pragma unroll
        for (int off = 1; off < 32; off <<= 1) {
            int y = __shfl_up_sync(0xffffffffu, s, off);
            if (lane >= off) s += y;
        }
        if (lane == 31) wsum[wid] = s;
        __syncthreads();
        if (wid == 0) {
            int ws = wsum[lane];
#pragma unroll
            for (int off = 1; off < 32; off <<= 1) {
                int y = __shfl_up_sync(0xffffffffu, ws, off);
                if (lane >= off) ws += y;
            }
            wsum[lane] = ws;
        }
        __syncthreads();
        int wbase = (wid == 0) ? 0 : wsum[wid - 1];
        int incl = carry_s + wbase + s;
        if (i < NN) g_off[i + 1] = incl;
        __syncthreads();
        if (t == 1023) carry_s = incl;
        __syncthreads();
    }
}

// ---------------- CSR fill: bucket edges by dst, weight = dinv[s]*dinv[d] ---
__global__ void k_fill(const void* __restrict__ ei) {
    int e = blockIdx.x * blockDim.x + threadIdx.x;
    if (e >= EE) return;
    int is64 = g_idx64;
    int s = ldidx(ei, e, is64);
    int d = ldidx(ei, (long long)EE + e, is64);
    float w = g_dinv[s] * g_dinv[d];
    int pos = g_off[d] + atomicAdd(&g_cur[d], 1);
    g_epack[pos] = make_int2(s, __float_as_int(w));
}

// ---------------- GEMM: H[n][o] = sum_c f(X[n][c]) * W[o][c] ----------------
// Wd: duplicated [c][2o] layout. Packed fp32x2 FMAs over row pairs.
// BN: apply y = relu(x*aff[c]+aff[CH+c]) to the X tile on load.
template <int OC, bool BN>
__global__ void __launch_bounds__(256) k_gemm(const float* __restrict__ X,
                                              const float* __restrict__ Wd,
                                              float* __restrict__ H,
                                              const float* __restrict__ aff,
                                              int nrows) {
    constexpr int K = 128, BM = 64, XS = BM + 4;
    constexpr int TPG = OC / 4;           // threads per row-group (32 or 16)
    constexpr int RPT = BM / (256 / TPG); // rows per thread (8 or 4)
    __shared__ __align__(16) float Xs[K * XS];

    int t = threadIdx.x;
    int row0 = blockIdx.x * BM;

    // Load X tile, transposed: Xs[c][r]; optionally fuse BN affine + ReLU
#pragma unroll
    for (int j = 0; j < (BM * K) / 256; j++) {
        int idx = t + j * 256;
        int r = idx >> 7, c = idx & 127;
        int row = row0 + r;
        float v = (row < nrows) ? X[row * K + c] : 0.0f;
        if (BN) v = fmaxf(fmaf(v, aff[c], aff[CH + c]), 0.0f);
        Xs[c * XS + r] = v;
    }
    __syncthreads();

    int o0 = (t % TPG) * 4;
    int r0 = (t / TPG) * RPT;

    unsigned long long acc2[RPT / 2][4];
#pragma unroll
    for (int p = 0; p < RPT / 2; p++)
#pragma unroll
        for (int l = 0; l < 4; l++) acc2[p][l] = 0ull;

#pragma unroll 4
    for (int c = 0; c < K; c++) {
        // duplicated weights: {w0,w0},{w1,w1},{w2,w2},{w3,w3}
        const ulonglong2* wrow =
            reinterpret_cast<const ulonglong2*>(Wd + c * 2 * OC + 2 * o0);
        ulonglong2 wa = wrow[0];
        ulonglong2 wb = wrow[1];
#pragma unroll
        for (int jj = 0; jj < RPT / 4; jj++) {
            // xp.x = {x_r, x_r+1}, xp.y = {x_r+2, x_r+3}
            const ulonglong2 xp =
                *reinterpret_cast<const ulonglong2*>(Xs + c * XS + r0 + 4 * jj);
            ffma2(acc2[2 * jj + 0][0], xp.x, wa.x);
            ffma2(acc2[2 * jj + 0][1], xp.x, wa.y);
            ffma2(acc2[2 * jj + 0][2], xp.x, wb.x);
            ffma2(acc2[2 * jj + 0][3], xp.x, wb.y);
            ffma2(acc2[2 * jj + 1][0], xp.y, wa.x);
            ffma2(acc2[2 * jj + 1][1], xp.y, wa.y);
            ffma2(acc2[2 * jj + 1][2], xp.y, wb.x);
            ffma2(acc2[2 * jj + 1][3], xp.y, wb.y);
        }
    }

#pragma unroll
    for (int p = 0; p < RPT / 2; p++) {
        int rowa = row0 + r0 + 2 * p;
        int rowb = rowa + 1;
        if (rowa < nrows) {
            float4 ov = make_float4(f2lo(acc2[p][0]), f2lo(acc2[p][1]),
                                    f2lo(acc2[p][2]), f2lo(acc2[p][3]));
            *reinterpret_cast<float4*>(H + rowa * OC + o0) = ov;
        }
        if (rowb < nrows) {
            float4 ov = make_float4(f2hi(acc2[p][0]), f2hi(acc2[p][1]),
                                    f2hi(acc2[p][2]), f2hi(acc2[p][3]));
            *reinterpret_cast<float4*>(H + rowb * OC + o0) = ov;
        }
    }
}

// ---------------- gather-aggregate (CSR by dst), fused self-loop + bias -----
// One warp per dst row (C=128) or per 2 rows (C=64). No atomics on features.
// STATS: block-level BN sum/sumsq reduction -> per-block global atomics.
template <int C, bool STATS>
__global__ void __launch_bounds__(256) k_gather(const float4* __restrict__ h,
                                                const float* __restrict__ bias,
                                                float4* __restrict__ agg,
                                                float* stats) {
    constexpr int L = C / 4;          // float4 per row (32 or 16)
    constexpr int RPW = 128 / C;      // rows per warp (1 or 2)
    constexpr int LPR = 32 / RPW;     // lanes per row (32 or 16)
    __shared__ float4 sb[8 * 32];     // stats staging (used when STATS)

    int t = threadIdx.x;
    int warp = t >> 5, lane = t & 31;
    int row = blockIdx.x * 8 * RPW + warp * RPW + lane / LPR;
    int sub = lane % LPR;

    float4 acc = make_float4(0.f, 0.f, 0.f, 0.f);
    if (row < NN) {
        float di = g_dinv[row];
        float sw = di * di;
        float4 b4 = reinterpret_cast<const float4*>(bias)[sub];
        float4 v = h[row * L + sub];
        acc.x = fmaf(v.x, sw, b4.x);
        acc.y = fmaf(v.y, sw, b4.y);
        acc.z = fmaf(v.z, sw, b4.z);
        acc.w = fmaf(v.w, sw, b4.w);

        int e = g_off[row];
        int end = g_off[row + 1];
        for (; e + 1 < end; e += 2) {
            int2 p0 = g_epack[e];
            int2 p1 = g_epack[e + 1];
            float w0 = __int_as_float(p0.y);
            float w1 = __int_as_float(p1.y);
            float4 v0 = h[p0.x * L + sub];
            float4 v1 = h[p1.x * L + sub];
            acc.x = fmaf(w0, v0.x, acc.x); acc.x = fmaf(w1, v1.x, acc.x);
            acc.y = fmaf(w0, v0.y, acc.y); acc.y = fmaf(w1, v1.y, acc.y);
            acc.z = fmaf(w0, v0.z, acc.z); acc.z = fmaf(w1, v1.z, acc.z);
            acc.w = fmaf(w0, v0.w, acc.w); acc.w = fmaf(w1, v1.w, acc.w);
        }
        if (e < end) {
            int2 p0 = g_epack[e];
            float w0 = __int_as_float(p0.y);
            float4 v0 = h[p0.x * L + sub];
            acc.x = fmaf(w0, v0.x, acc.x);
            acc.y = fmaf(w0, v0.y, acc.y);
            acc.z = fmaf(w0, v0.z, acc.z);
            acc.w = fmaf(w0, v0.w, acc.w);
        }
        agg[row * L + sub] = acc;
    }

    if (STATS) {
        // C==128 path only: warp==row, sub==lane covers channels [4*sub,4*sub+4)
        sb[warp * 32 + sub] = acc;
        __syncthreads();
        if (t < CH) {
            int c4 = t >> 2, k = t & 3;
            float s = 0.f, ss = 0.f;
#pragma unroll
            for (int w = 0; w < 8; w++) {
                const float4 vv = sb[w * 32 + c4];
                float x = (k == 0) ? vv.x : (k == 1) ? vv.y : (k == 2) ? vv.z : vv.w;
                s += x;
                ss += x * x;
            }
            atomicAdd(&stats[t], s);
            atomicAdd(&stats[CH + t], ss);
        }
    }
}

// ---------------- BN finalize: stats -> affine (scale, shift) ---------------
__global__ void k_finalize(const float* __restrict__ sums, const float* __restrict__ gamma,
                           const float* __restrict__ beta, float* aff) {
    int t = threadIdx.x; // 128
    const float inv = 1.0f / (float)NN;
    float mean = sums[t] * inv;
    float var = sums[CH + t] * inv - mean * mean;
    float sc = gamma[t] * rsqrtf(var + BN_EPS);
    aff[t] = sc;
    aff[CH + t] = beta[t] - mean * sc;
}

// ---------------- launch ----------------------------------------------------
extern "C" void kernel_launch(void* const* d_in, const int* in_sizes, int n_in,
                              void* d_out, int out_size) {
    const float* x  = (const float*)d_in[0];
    const void*  ei = d_in[1];
    const float* W1 = (const float*)d_in[2];
    const float* b1 = (const float*)d_in[3];
    const float* W2 = (const float*)d_in[4];
    const float* b2 = (const float*)d_in[5];
    const float* W3 = (const float*)d_in[6];
    const float* b3 = (const float*)d_in[7];
    const float* g1 = (const float*)d_in[8];
    const float* t1 = (const float*)d_in[9];
    const float* g2 = (const float*)d_in[10];
    const float* t2 = (const float*)d_in[11];
    float* out = (float*)d_out;

    void *pA_, *pB_, *pW1_, *pW2_, *pW3_, *pSt_, *pAf_;
    cudaGetSymbolAddress(&pA_, g_bufA);
    cudaGetSymbolAddress(&pB_, g_bufB);
    cudaGetSymbolAddress(&pW1_, g_Wd1);
    cudaGetSymbolAddress(&pW2_, g_Wd2);
    cudaGetSymbolAddress(&pW3_, g_Wd3);
    cudaGetSymbolAddress(&pSt_, g_stats);
    cudaGetSymbolAddress(&pAf_, g_aff);
    float* pA = (float*)pA_;
    float* pB = (float*)pB_;
    float* pW1 = (float*)pW1_;
    float* pW2 = (float*)pW2_;
    float* pW3 = (float*)pW3_;
    float* pSt = (float*)pSt_;
    float* pAf = (float*)pAf_;

    const int TPB = 256;
    const int gN = (NN + TPB - 1) / TPB;
    const int gE = (EE + TPB - 1) / TPB;
    const int gGemm = (NN + 63) / 64;
    const int gGath128 = (NN + 7) / 8;    // 6250
    const int gGath64  = (NN + 15) / 16;  // 3125

    // ---- preprocessing: CSR by dst + norms ----
    k_init<<<gN, TPB>>>((const int*)ei);
    k_prepw<<<(CH * CH + TPB - 1) / TPB, TPB>>>(W1, W2, W3);
    k_degree<<<gE, TPB>>>(ei);
    k_scan<<<1, 1024>>>();
    k_dinv<<<gN, TPB>>>();
    k_fill<<<gE, TPB>>>(ei);

    // ---- layer 1 ----
    k_gemm<CH, false><<<gGemm, TPB>>>(x, pW1, pA, nullptr, NN);
    k_gather<CH, true><<<gGath128, TPB>>>((const float4*)pA, b1, (float4*)pB, pSt);
    k_finalize<<<1, 128>>>(pSt, g1, t1, pAf);

    // ---- layer 2 (BN1+ReLU fused into GEMM input) ----
    k_gemm<CH, true><<<gGemm, TPB>>>(pB, pW2, pA, pAf, NN);
    k_gather<CH, true><<<gGath128, TPB>>>((const float4*)pA, b2, (float4*)pB, pSt + 256);
    k_finalize<<<1, 128>>>(pSt + 256, g2, t2, pAf + 256);

    // ---- layer 3 (BN2+ReLU fused into GEMM input; 64 out ch; -> d_out) ----
    k_gemm<CO, true><<<gGemm, TPB>>>(pB, pW3, pA, pAf + 256, NN);
    k_gather<CO, false><<<gGath64, TPB>>>((const float4*)pA, b3, (float4*)out, nullptr);

    (void)in_sizes; (void)n_in; (void)out_size;
}

// round 10
// speedup vs baseline: 1.2473x; 1.2325x over previous
#include <cuda_runtime.h>
#include <cuda_bf16.h>

// GCN: N=50000 nodes, E=800000 edges, 128 -> 128 -> 128 -> 64
#define NN 50000
#define EE 800000
#define CH 128
#define CO 64
#define BN_EPS 1e-5f

#define SCAN_CHUNK 1024
#define SCAN_NB ((NN + SCAN_CHUNK - 1) / SCAN_CHUNK)   // 49

// ---------------- scratch (static device allocations only) ----------------
__device__ float g_dinv[NN];
__device__ int   g_cnt[NN];          // in-degree (no self loop)
__device__ int   g_cur[NN];          // CSR fill cursors
__device__ int   g_off[NN + 1];      // CSR row offsets (by dst)
__device__ int   g_bsum[SCAN_NB];    // scan block totals
__device__ int   g_bpre[SCAN_NB];    // scan block exclusive prefixes
__device__ int2  g_epack[EE];        // {src, w(bits)} sorted by dst
__device__ float g_bufA[NN * CH];    // GEMM output h
__device__ float g_bufB[NN * CH];    // aggregation output
__device__ float g_Wd1[CH * CH * 2]; // W transposed + duplicated: [c][2o] (pairs)
__device__ float g_Wd2[CH * CH * 2];
__device__ float g_Wd3[CH * CO * 2];
__device__ float g_stats[512];       // L1: sum[0:128) sumsq[128:256); L2: +256
__device__ float g_aff[512];         // L1: scale[0:128) shift[128:256); L2: +256
__device__ int   g_idx64;

// ---------------- helpers ----------------
__device__ __forceinline__ int ldidx(const void* p, long long i, int is64) {
    if (is64) return (int)((const long long*)p)[i];
    return ((const int*)p)[i];
}

__device__ __forceinline__ void ffma2(unsigned long long& d, unsigned long long a,
                                      unsigned long long b) {
    asm("fma.rn.f32x2 %0, %1, %2, %0;" : "+l"(d) : "l"(a), "l"(b));
}
__device__ __forceinline__ float f2lo(unsigned long long v) {
    return __uint_as_float((unsigned)(v & 0xffffffffull));
}
__device__ __forceinline__ float f2hi(unsigned long long v) {
    return __uint_as_float((unsigned)(v >> 32));
}

// ---------------- init: zero counters/stats, detect idx dtype ----------------
__global__ void k_init(const int* ei32) {
    int i = blockIdx.x * blockDim.x + threadIdx.x;
    if (i < NN) { g_cnt[i] = 0; g_cur[i] = 0; }
    if (i < 512) g_stats[i] = 0.0f;
    if (i == 0) {
        int z = 1;
#pragma unroll
        for (int j = 0; j < 32; j++)
            if (ei32[2 * j + 1] != 0) z = 0;
        g_idx64 = z;
    }
}

// ---------------- weights: transpose to [c][o] and duplicate each value -----
__global__ void k_prepw(const float* __restrict__ W1, const float* __restrict__ W2,
                        const float* __restrict__ W3) {
    int i = blockIdx.x * blockDim.x + threadIdx.x;
    if (i < CH * CH) {
        int o = i / CH, c = i % CH;
        float v1 = W1[i], v2 = W2[i];
        g_Wd1[c * 2 * CH + 2 * o] = v1; g_Wd1[c * 2 * CH + 2 * o + 1] = v1;
        g_Wd2[c * 2 * CH + 2 * o] = v2; g_Wd2[c * 2 * CH + 2 * o + 1] = v2;
    }
    if (i < CO * CH) {
        int o = i / CH, c = i % CH;
        float v3 = W3[i];
        g_Wd3[c * 2 * CO + 2 * o] = v3; g_Wd3[c * 2 * CO + 2 * o + 1] = v3;
    }
}

// ---------------- in-degree counting at dst ----------------
__global__ void k_degree(const void* __restrict__ ei) {
    int e = blockIdx.x * blockDim.x + threadIdx.x;
    if (e >= EE) return;
    int is64 = g_idx64;
    int d = ldidx(ei, (long long)EE + e, is64);
    atomicAdd(&g_cnt[d], 1);
}

// ---------------- multi-block exclusive scan of g_cnt -> g_off --------------
// Stage A: per-block (1024-elem chunk) totals.
__global__ void __launch_bounds__(256) k_scanA() {
    int b = blockIdx.x, t = threadIdx.x, lane = t & 31, wid = t >> 5;
    int i0 = b * SCAN_CHUNK + t * 4;
    int s = 0;
#pragma unroll
    for (int j = 0; j < 4; j++) {
        int i = i0 + j;
        if (i < NN) s += g_cnt[i];
    }
#pragma unroll
    for (int off = 16; off > 0; off >>= 1) s += __shfl_down_sync(0xffffffffu, s, off);
    __shared__ int ws[8];
    if (lane == 0) ws[wid] = s;
    __syncthreads();
    if (t == 0) {
        int tot = 0;
#pragma unroll
        for (int j = 0; j < 8; j++) tot += ws[j];
        g_bsum[b] = tot;
    }
}

// Stage B: one warp scans the 49 block totals -> exclusive prefixes.
__global__ void k_scanB() {
    int l = threadIdx.x; // 32
    int v0 = (2 * l < SCAN_NB) ? g_bsum[2 * l] : 0;
    int v1 = (2 * l + 1 < SCAN_NB) ? g_bsum[2 * l + 1] : 0;
    int s = v0 + v1;
    int incl = s;
#pragma unroll
    for (int off = 1; off < 32; off <<= 1) {
        int y = __shfl_up_sync(0xffffffffu, incl, off);
        if (l >= off) incl += y;
    }
    int excl = incl - s;
    if (2 * l < SCAN_NB) g_bpre[2 * l] = excl;
    if (2 * l + 1 < SCAN_NB) g_bpre[2 * l + 1] = excl + v0;
}

// Stage C: local scan + add block base; also fused dinv = rsqrt(deg+1).
__global__ void __launch_bounds__(256) k_scanC() {
    int b = blockIdx.x, t = threadIdx.x, lane = t & 31, wid = t >> 5;
    int base = g_bpre[b];
    int i0 = b * SCAN_CHUNK + t * 4;
    int v[4];
    int s = 0;
#pragma unroll
    for (int j = 0; j < 4; j++) {
        int i = i0 + j;
        v[j] = (i < NN) ? g_cnt[i] : 0;
        s += v[j];
    }
    int incl = s;
#pragma unroll
    for (int off = 1; off < 32; off <<= 1) {
        int y = __shfl_up_sync(0xffffffffu, incl, off);
        if (lane >= off) incl += y;
    }
    __shared__ int ws[8];
    if (lane == 31) ws[wid] = incl;
    __syncthreads();
    int wbase = 0;
#pragma unroll
    for (int j = 0; j < 8; j++)
        if (j < wid) wbase += ws[j];
    int run = base + wbase + (incl - s);
#pragma unroll
    for (int j = 0; j < 4; j++) {
        int i = i0 + j;
        run += v[j];
        if (i < NN) {
            g_off[i + 1] = run;
            g_dinv[i] = rsqrtf((float)v[j] + 1.0f);
        }
    }
    if (b == 0 && t == 0) g_off[0] = 0;
}

// ---------------- CSR fill: bucket edges by dst, weight = dinv[s]*dinv[d] ---
__global__ void k_fill(const void* __restrict__ ei) {
    int e = blockIdx.x * blockDim.x + threadIdx.x;
    if (e >= EE) return;
    int is64 = g_idx64;
    int s = ldidx(ei, e, is64);
    int d = ldidx(ei, (long long)EE + e, is64);
    float w = g_dinv[s] * g_dinv[d];
    int pos = g_off[d] + atomicAdd(&g_cur[d], 1);
    g_epack[pos] = make_int2(s, __float_as_int(w));
}

// ---------------- GEMM: H[n][o] = sum_c f(X[n][c]) * W[o][c] ----------------
template <int OC, bool BN>
__global__ void __launch_bounds__(256) k_gemm(const float* __restrict__ X,
                                              const float* __restrict__ Wd,
                                              float* __restrict__ H,
                                              const float* __restrict__ aff,
                                              int nrows) {
    constexpr int K = 128, BM = 64, XS = BM + 4;
    constexpr int TPG = OC / 4;           // threads per row-group (32 or 16)
    constexpr int RPT = BM / (256 / TPG); // rows per thread (8 or 4)
    __shared__ __align__(16) float Xs[K * XS];

    int t = threadIdx.x;
    int row0 = blockIdx.x * BM;

#pragma unroll
    for (int j = 0; j < (BM * K) / 256; j++) {
        int idx = t + j * 256;
        int r = idx >> 7, c = idx & 127;
        int row = row0 + r;
        float v = (row < nrows) ? X[row * K + c] : 0.0f;
        if (BN) v = fmaxf(fmaf(v, aff[c], aff[CH + c]), 0.0f);
        Xs[c * XS + r] = v;
    }
    __syncthreads();

    int o0 = (t % TPG) * 4;
    int r0 = (t / TPG) * RPT;

    unsigned long long acc2[RPT / 2][4];
#pragma unroll
    for (int p = 0; p < RPT / 2; p++)
#pragma unroll
        for (int l = 0; l < 4; l++) acc2[p][l] = 0ull;

#pragma unroll 4
    for (int c = 0; c < K; c++) {
        const ulonglong2* wrow =
            reinterpret_cast<const ulonglong2*>(Wd + c * 2 * OC + 2 * o0);
        ulonglong2 wa = wrow[0];
        ulonglong2 wb = wrow[1];
#pragma unroll
        for (int jj = 0; jj < RPT / 4; jj++) {
            const ulonglong2 xp =
                *reinterpret_cast<const ulonglong2*>(Xs + c * XS + r0 + 4 * jj);
            ffma2(acc2[2 * jj + 0][0], xp.x, wa.x);
            ffma2(acc2[2 * jj + 0][1], xp.x, wa.y);
            ffma2(acc2[2 * jj + 0][2], xp.x, wb.x);
            ffma2(acc2[2 * jj + 0][3], xp.x, wb.y);
            ffma2(acc2[2 * jj + 1][0], xp.y, wa.x);
            ffma2(acc2[2 * jj + 1][1], xp.y, wa.y);
            ffma2(acc2[2 * jj + 1][2], xp.y, wb.x);
            ffma2(acc2[2 * jj + 1][3], xp.y, wb.y);
        }
    }

#pragma unroll
    for (int p = 0; p < RPT / 2; p++) {
        int rowa = row0 + r0 + 2 * p;
        int rowb = rowa + 1;
        if (rowa < nrows) {
            float4 ov = make_float4(f2lo(acc2[p][0]), f2lo(acc2[p][1]),
                                    f2lo(acc2[p][2]), f2lo(acc2[p][3]));
            *reinterpret_cast<float4*>(H + rowa * OC + o0) = ov;
        }
        if (rowb < nrows) {
            float4 ov = make_float4(f2hi(acc2[p][0]), f2hi(acc2[p][1]),
                                    f2hi(acc2[p][2]), f2hi(acc2[p][3]));
            *reinterpret_cast<float4*>(H + rowb * OC + o0) = ov;
        }
    }
}

// ---------------- gather-aggregate (CSR by dst), fused self-loop + bias -----
// One warp per dst row (C=128) or per 2 rows (C=64). Unroll 4 edges -> MLP 4.
template <int C, bool STATS>
__global__ void __launch_bounds__(256) k_gather(const float4* __restrict__ h,
                                                const float* __restrict__ bias,
                                                float4* __restrict__ agg,
                                                float* stats) {
    constexpr int L = C / 4;          // float4 per row (32 or 16)
    constexpr int RPW = 128 / C;      // rows per warp (1 or 2)
    constexpr int LPR = 32 / RPW;     // lanes per row (32 or 16)
    __shared__ float4 sb[8 * 32];

    int t = threadIdx.x;
    int warp = t >> 5, lane = t & 31;
    int row = blockIdx.x * 8 * RPW + warp * RPW + lane / LPR;
    int sub = lane % LPR;

    float4 acc = make_float4(0.f, 0.f, 0.f, 0.f);
    if (row < NN) {
        float di = g_dinv[row];
        float sw = di * di;
        float4 b4 = reinterpret_cast<const float4*>(bias)[sub];
        float4 v = h[row * L + sub];
        acc.x = fmaf(v.x, sw, b4.x);
        acc.y = fmaf(v.y, sw, b4.y);
        acc.z = fmaf(v.z, sw, b4.z);
        acc.w = fmaf(v.w, sw, b4.w);

        int e = g_off[row];
        int end = g_off[row + 1];
        // 4-wide unroll: 4 edge records then 4 independent feature gathers.
        for (; e + 3 < end; e += 4) {
            int2 p0 = g_epack[e];
            int2 p1 = g_epack[e + 1];
            int2 p2 = g_epack[e + 2];
            int2 p3 = g_epack[e + 3];
            float4 v0 = h[p0.x * L + sub];
            float4 v1 = h[p1.x * L + sub];
            float4 v2 = h[p2.x * L + sub];
            float4 v3 = h[p3.x * L + sub];
            float w0 = __int_as_float(p0.y), w1 = __int_as_float(p1.y);
            float w2 = __int_as_float(p2.y), w3 = __int_as_float(p3.y);
            acc.x = fmaf(w0, v0.x, acc.x); acc.y = fmaf(w0, v0.y, acc.y);
            acc.z = fmaf(w0, v0.z, acc.z); acc.w = fmaf(w0, v0.w, acc.w);
            acc.x = fmaf(w1, v1.x, acc.x); acc.y = fmaf(w1, v1.y, acc.y);
            acc.z = fmaf(w1, v1.z, acc.z); acc.w = fmaf(w1, v1.w, acc.w);
            acc.x = fmaf(w2, v2.x, acc.x); acc.y = fmaf(w2, v2.y, acc.y);
            acc.z = fmaf(w2, v2.z, acc.z); acc.w = fmaf(w2, v2.w, acc.w);
            acc.x = fmaf(w3, v3.x, acc.x); acc.y = fmaf(w3, v3.y, acc.y);
            acc.z = fmaf(w3, v3.z, acc.z); acc.w = fmaf(w3, v3.w, acc.w);
        }
        for (; e < end; e++) {
            int2 p0 = g_epack[e];
            float w0 = __int_as_float(p0.y);
            float4 v0 = h[p0.x * L + sub];
            acc.x = fmaf(w0, v0.x, acc.x);
            acc.y = fmaf(w0, v0.y, acc.y);
            acc.z = fmaf(w0, v0.z, acc.z);
            acc.w = fmaf(w0, v0.w, acc.w);
        }
        agg[row * L + sub] = acc;
    }

    if (STATS) {
        sb[warp * 32 + sub] = acc;
        __syncthreads();
        if (t < CH) {
            int c4 = t >> 2, k = t & 3;
            float s = 0.f, ss = 0.f;
#pragma unroll
            for (int w = 0; w < 8; w++) {
                const float4 vv = sb[w * 32 + c4];
                float x = (k == 0) ? vv.x : (k == 1) ? vv.y : (k == 2) ? vv.z : vv.w;
                s += x;
                ss += x * x;
            }
            atomicAdd(&stats[t], s);
            atomicAdd(&stats[CH + t], ss);
        }
    }
}

// ---------------- BN finalize: stats -> affine (scale, shift) ---------------
__global__ void k_finalize(const float* __restrict__ sums, const float* __restrict__ gamma,
                           const float* __restrict__ beta, float* aff) {
    int t = threadIdx.x; // 128
    const float inv = 1.0f / (float)NN;
    float mean = sums[t] * inv;
    float var = sums[CH + t] * inv - mean * mean;
    float sc = gamma[t] * rsqrtf(var + BN_EPS);
    aff[t] = sc;
    aff[CH + t] = beta[t] - mean * sc;
}

// ---------------- launch ----------------------------------------------------
extern "C" void kernel_launch(void* const* d_in, const int* in_sizes, int n_in,
                              void* d_out, int out_size) {
    const float* x  = (const float*)d_in[0];
    const void*  ei = d_in[1];
    const float* W1 = (const float*)d_in[2];
    const float* b1 = (const float*)d_in[3];
    const float* W2 = (const float*)d_in[4];
    const float* b2 = (const float*)d_in[5];
    const float* W3 = (const float*)d_in[6];
    const float* b3 = (const float*)d_in[7];
    const float* g1 = (const float*)d_in[8];
    const float* t1 = (const float*)d_in[9];
    const float* g2 = (const float*)d_in[10];
    const float* t2 = (const float*)d_in[11];
    float* out = (float*)d_out;

    void *pA_, *pB_, *pW1_, *pW2_, *pW3_, *pSt_, *pAf_;
    cudaGetSymbolAddress(&pA_, g_bufA);
    cudaGetSymbolAddress(&pB_, g_bufB);
    cudaGetSymbolAddress(&pW1_, g_Wd1);
    cudaGetSymbolAddress(&pW2_, g_Wd2);
    cudaGetSymbolAddress(&pW3_, g_Wd3);
    cudaGetSymbolAddress(&pSt_, g_stats);
    cudaGetSymbolAddress(&pAf_, g_aff);
    float* pA = (float*)pA_;
    float* pB = (float*)pB_;
    float* pW1 = (float*)pW1_;
    float* pW2 = (float*)pW2_;
    float* pW3 = (float*)pW3_;
    float* pSt = (float*)pSt_;
    float* pAf = (float*)pAf_;

    const int TPB = 256;
    const int gN = (NN + TPB - 1) / TPB;
    const int gE = (EE + TPB - 1) / TPB;
    const int gGemm = (NN + 63) / 64;
    const int gGath128 = (NN + 7) / 8;    // 6250
    const int gGath64  = (NN + 15) / 16;  // 3125

    // ---- preprocessing: CSR by dst + norms ----
    k_init<<<gN, TPB>>>((const int*)ei);
    k_prepw<<<(CH * CH + TPB - 1) / TPB, TPB>>>(W1, W2, W3);
    k_degree<<<gE, TPB>>>(ei);
    k_scanA<<<SCAN_NB, 256>>>();
    k_scanB<<<1, 32>>>();
    k_scanC<<<SCAN_NB, 256>>>();
    k_fill<<<gE, TPB>>>(ei);

    // ---- layer 1 ----
    k_gemm<CH, false><<<gGemm, TPB>>>(x, pW1, pA, nullptr, NN);
    k_gather<CH, true><<<gGath128, TPB>>>((const float4*)pA, b1, (float4*)pB, pSt);
    k_finalize<<<1, 128>>>(pSt, g1, t1, pAf);

    // ---- layer 2 (BN1+ReLU fused into GEMM input) ----
    k_gemm<CH, true><<<gGemm, TPB>>>(pB, pW2, pA, pAf, NN);
    k_gather<CH, true><<<gGath128, TPB>>>((const float4*)pA, b2, (float4*)pB, pSt + 256);
    k_finalize<<<1, 128>>>(pSt + 256, g2, t2, pAf + 256);

    // ---- layer 3 (BN2+ReLU fused into GEMM input; 64 out ch; -> d_out) ----
    k_gemm<CO, true><<<gGemm, TPB>>>(pB, pW3, pA, pAf + 256, NN);
    k_gather<CO, false><<<gGath64, TPB>>>((const float4*)pA, b3, (float4*)out, nullptr);

    (void)in_sizes; (void)n_in; (void)out_size;
}